// round 12
// baseline (speedup 1.0000x reference)
#include <cuda_runtime.h>
#include <cuda_bf16.h>
#include <cstdint>
#include <math.h>

// Problem constants
#define BB 2
#define SS 2048
#define EE 2048
#define HH 16
#define DD 128
#define MROWS (BB * SS)          // 4096
#define QKV_N (3 * EE)           // 6144

// ---------------- scratch (device globals: allocation-free) ----------------
__device__ float g_Q   [(size_t)BB * HH * SS * DD];     // [b,h,s,d] roped, scaled, tf32
__device__ float g_K   [(size_t)BB * HH * SS * DD];     // [b,h,s,d] roped, tf32
__device__ float g_Vt  [(size_t)BB * HH * DD * SS];     // [b,h,d,s] tf32
__device__ float g_y   [(size_t)MROWS * EE];            // [b,s,h,d], tf32-rounded
__device__ float2 g_rope[(size_t)SS * 64];              // (cos,sin) per (s, i)

// ======================= helpers ===========================================
__device__ __forceinline__ uint32_t smem_u32(const void* p) {
    uint32_t a;
    asm("{ .reg .u64 t; cvta.to.shared.u64 t, %1; cvt.u32.u64 %0, t; }"
        : "=r"(a) : "l"(p));
    return a;
}

__device__ __forceinline__ float to_tf32(float x) {
    uint32_t u;
    asm("cvt.rna.tf32.f32 %0, %1;" : "=r"(u) : "f"(x));
    return __uint_as_float(u);
}

__device__ __forceinline__ uint32_t tf32_u32(uint32_t x) {
    uint32_t u;
    asm("cvt.rna.tf32.f32 %0, %1;" : "=r"(u) : "f"(__uint_as_float(x)));
    return u;
}

#define CPA16(dst, src) \
    asm volatile("cp.async.cg.shared.global [%0], [%1], 16;" :: "r"(dst), "l"(src))
#define CPA_COMMIT()  asm volatile("cp.async.commit_group;" ::: "memory")
#define CPA_WAIT1()   asm volatile("cp.async.wait_group 1;" ::: "memory")
#define CPA_WAIT0()   asm volatile("cp.async.wait_group 0;" ::: "memory")

#define LDSM4(r, addr)                                                        \
    asm volatile("ldmatrix.sync.aligned.m8n8.x4.shared.b16 {%0,%1,%2,%3}, [%4];" \
        : "=r"((r)[0]), "=r"((r)[1]), "=r"((r)[2]), "=r"((r)[3]) : "r"(addr))

#define MMA_TF32(c, a, b0, b1)                                                \
    asm volatile("mma.sync.aligned.m16n8k8.row.col.f32.tf32.tf32.f32 "        \
        "{%0,%1,%2,%3}, {%4,%5,%6,%7}, {%8,%9}, {%0,%1,%2,%3};"               \
        : "+f"((c)[0]), "+f"((c)[1]), "+f"((c)[2]), "+f"((c)[3])              \
        : "r"((a)[0]), "r"((a)[1]), "r"((a)[2]), "r"((a)[3]), "r"(b0), "r"(b1))

// ============ mma.sync tf32 GEMM: C[M,N] = A[M,K] @ B[N,K]^T ===============
// CTA 128x128, 256 thr / 8 warps (4m x 2n), warptile 32x64, 3-stage cp.async
// 2 CTAs per SM. FUSE=1: QKV epilogue (RoPE q/k, transpose v), FUSE=0: plain C.
// RA/RB: tf32-RNA-round A/B fragments in-register (replaces rounding prepasses).
#define GP 36                                // SMEM pitch (floats), %32==4
#define BOFF (128 * GP * 4)                  // B offset within stage (bytes)
#define STG_B ((128 + 128) * GP * 4)         // 36864 bytes
#define GEMM_SMEM (3 * STG_B)                // 110592 bytes

__device__ __forceinline__ void g2s_stage(const float* A, const float* B, int K,
                                          uint32_t stg, int tid) {
#pragma unroll
    for (int j = 0; j < 4; j++) {            // A: 128 rows x 8 chunks
        int cid = tid + j * 256;
        int row = cid >> 3, chk = cid & 7;
        CPA16(stg + (uint32_t)(row * GP + chk * 4) * 4,
              A + (size_t)row * K + chk * 4);
    }
#pragma unroll
    for (int j = 0; j < 4; j++) {            // B: 128 rows x 8 chunks
        int cid = tid + j * 256;
        int row = cid >> 3, chk = cid & 7;
        CPA16(stg + BOFF + (uint32_t)(row * GP + chk * 4) * 4,
              B + (size_t)row * K + chk * 4);
    }
}

template<int FUSE, int RA, int RB>
__global__ __launch_bounds__(256, 2)
void gemm_k(const float* __restrict__ A, const float* __restrict__ B,
            float* __restrict__ C,
            float* __restrict__ Qo, float* __restrict__ Ko, float* __restrict__ Vo,
            const float2* __restrict__ rt, int N, int K) {
    extern __shared__ char smem[];
    const uint32_t sbase = smem_u32(smem);
    const int tid  = threadIdx.x;
    const int wid  = tid >> 5;
    const int lane = tid & 31;
    const int wm   = wid >> 1;               // 0..3 (32 rows)
    const int wn   = wid & 1;                // 0..1 (64 cols)
    const int m0 = blockIdx.y * 128;
    const int n0 = blockIdx.x * 128;
    const int iters = K >> 5;

    const float* Ab = A + (size_t)m0 * K;
    const float* Bb = B + (size_t)n0 * K;

    float c[2][8][4];
#pragma unroll
    for (int i = 0; i < 2; i++)
#pragma unroll
        for (int j = 0; j < 8; j++)
#pragma unroll
            for (int q = 0; q < 4; q++) c[i][j][q] = 0.f;

    const int sub = lane >> 3;
    const int r8  = lane & 7;
    const uint32_t aoff = (uint32_t)((wm * 32 + (sub & 1) * 8 + r8) * GP + (sub >> 1) * 4) * 4;
    const uint32_t boff = BOFF + (uint32_t)((wn * 64 + (sub >> 1) * 8 + r8) * GP + (sub & 1) * 4) * 4;

    g2s_stage(Ab, Bb, K, sbase, tid);                   CPA_COMMIT();
    g2s_stage(Ab + 32, Bb + 32, K, sbase + STG_B, tid); CPA_COMMIT();

    for (int i = 0; i < iters; i++) {
        CPA_WAIT1();
        __syncthreads();
        if (i + 2 < iters) {
            uint32_t stg = sbase + (uint32_t)((i + 2) % 3) * STG_B;
            g2s_stage(Ab + (i + 2) * 32, Bb + (i + 2) * 32, K, stg, tid);
            CPA_COMMIT();
        }
        const uint32_t ab = sbase + (uint32_t)(i % 3) * STG_B + aoff;
        const uint32_t bb = sbase + (uint32_t)(i % 3) * STG_B + boff;

#pragma unroll
        for (int kk = 0; kk < 4; kk++) {
            uint32_t a[2][4], bf[4][4];
#pragma unroll
            for (int im = 0; im < 2; im++)
                LDSM4(a[im], ab + (uint32_t)(im * 16 * GP) * 4 + kk * 32);
#pragma unroll
            for (int nt = 0; nt < 4; nt++)
                LDSM4(bf[nt], bb + (uint32_t)(nt * 16 * GP) * 4 + kk * 32);
            if (RA) {
#pragma unroll
                for (int im = 0; im < 2; im++)
#pragma unroll
                    for (int r = 0; r < 4; r++)
                        a[im][r] = tf32_u32(a[im][r]);
            }
            if (RB) {
#pragma unroll
                for (int nt = 0; nt < 4; nt++)
#pragma unroll
                    for (int r = 0; r < 4; r++)
                        bf[nt][r] = tf32_u32(bf[nt][r]);
            }
#pragma unroll
            for (int im = 0; im < 2; im++)
#pragma unroll
                for (int jn = 0; jn < 8; jn++)
                    MMA_TF32(c[im][jn], a[im],
                             bf[jn >> 1][(jn & 1) * 2],
                             bf[jn >> 1][(jn & 1) * 2 + 1]);
        }
    }

    const int g = lane >> 2, q = lane & 3;

    if (FUSE == 0) {
#pragma unroll
        for (int im = 0; im < 2; im++)
#pragma unroll
            for (int jn = 0; jn < 8; jn++) {
                int row = m0 + wm * 32 + im * 16 + g;
                int col = n0 + wn * 64 + jn * 8 + q * 2;
                *(float2*)&C[(size_t)row * N + col]       = make_float2(c[im][jn][0], c[im][jn][1]);
                *(float2*)&C[(size_t)(row + 8) * N + col] = make_float2(c[im][jn][2], c[im][jn][3]);
            }
    } else {
        // ---- fused QKV epilogue: stage tile, apply RoPE / transpose ----
        CPA_WAIT0();
        __syncthreads();                      // all warps done with stage SMEM
        float* Cs = (float*)smem;             // [128][132]
#pragma unroll
        for (int im = 0; im < 2; im++)
#pragma unroll
            for (int jn = 0; jn < 8; jn++) {
                int row = wm * 32 + im * 16 + g;
                int col = wn * 64 + jn * 8 + q * 2;
                *(float2*)&Cs[row * 132 + col]       = make_float2(c[im][jn][0], c[im][jn][1]);
                *(float2*)&Cs[(row + 8) * 132 + col] = make_float2(c[im][jn][2], c[im][jn][3]);
            }
        __syncthreads();

        const int hb   = n0 >> 7;             // 0..47
        const int type = hb >> 4;             // 0=q,1=k,2=v
        const int h    = hb & 15;
        const int b    = m0 >> 11;
        const int s0   = m0 & 2047;
        const size_t bh = (size_t)(b * HH + h);

        if (type < 2) {
            float* Out = (type == 0) ? Qo : Ko;
            const float scl = (type == 0) ? 0.088388347648318447f : 1.0f;
#pragma unroll
            for (int p = 0; p < 16; p++) {
                int idx = tid + p * 256;
                int row = idx >> 5, col = (idx & 31) * 4;
                int s = s0 + row;
                float4 v = *(float4*)&Cs[row * 132 + col];
                float4 w = *(float4*)&Cs[row * 132 + (col ^ 64)];
                float ov[4];
#pragma unroll
                for (int j = 0; j < 4; j++) {
                    int d = col + j;
                    float2 t = rt[s * 64 + (d & 63)];
                    float val  = (&v.x)[j];
                    float part = (&w.x)[j];
                    float r = (d < 64) ? -part : part;
                    ov[j] = to_tf32((val * t.x + r * t.y) * scl);
                }
                *(float4*)&Out[(bh * SS + s) * DD + col] =
                    make_float4(ov[0], ov[1], ov[2], ov[3]);
            }
        } else {
#pragma unroll
            for (int p = 0; p < 16; p++) {
                int idx = tid + p * 256;
                int d = idx >> 5, ch = idx & 31;
                float* vrow = Vo + (bh * DD + d) * SS + s0;
#pragma unroll
                for (int j = 0; j < 4; j++) {
                    int s = ch + j * 32;
                    vrow[s] = to_tf32(Cs[s * 132 + d]);
                }
            }
        }
    }
}

// ---------------- RoPE cos/sin table ---------------------------------------
__global__ void rope_table(float2* __restrict__ rt) {
    int idx = blockIdx.x * blockDim.x + threadIdx.x;   // SS*64
    int i = idx & 63, s = idx >> 6;
    float theta = (float)s * exp2f(-0.20762050593045998f * (float)i);
    float sn, cs;
    sincosf(theta, &sn, &cs);
    rt[idx] = make_float2(cs, sn);
}

// ---------------- Flash attention via mma.sync tf32 + cp.async -------------
#define QP 132                               // pitch (floats) for Qs/Ks
#define PP 68                                // pitch for Vs/Ps
#define ATTN2_SMEM ((128 * QP + 64 * QP + 128 * PP + 128 * PP) * 4)

__global__ __launch_bounds__(256, 1)
void attn_mma(const float* __restrict__ Qg_, const float* __restrict__ Kg_,
              const float* __restrict__ Vt_, float* __restrict__ Y) {
    extern __shared__ float sm[];
    float* Qs = sm;                          // [128][QP]  rows=qrow cols=d
    float* Ks = Qs + 128 * QP;               // [64][QP]   rows=kcol cols=d
    float* Vs = Ks + 64 * QP;                // [128][PP]  rows=d    cols=kcol
    float* Ps = Vs + 128 * PP;               // [128][PP]  rows=qrow cols=kcol

    const int tid  = threadIdx.x;
    const int wid  = tid >> 5;
    const int lane = tid & 31;
    const int qb = gridDim.x - 1 - blockIdx.x;   // heavy tiles first
    const int h  = blockIdx.y;
    const int b  = blockIdx.z;
    const int q0 = qb * 128;

    const size_t bh = (size_t)(b * HH + h);
    const float* Qg = Qg_ + bh * SS * DD;    // [s][d] (scaled, tf32)
    const float* Kg = Kg_ + bh * SS * DD;    // [s][d] (tf32)
    const float* Vg = Vt_ + bh * DD * SS;    // [d][s] (tf32)

    const uint32_t qsb = smem_u32(Qs);
    const uint32_t ksb = smem_u32(Ks);
    const uint32_t vsb = smem_u32(Vs);

    // prologue: async Q tile (group 1), K(0) (group 2), V(0) (group 3)
#pragma unroll
    for (int p = 0; p < 16; p++) {           // Q: 128 rows x 32 chunks
        int c = tid + p * 256;
        int row = c >> 5, ch = c & 31;
        CPA16(qsb + (uint32_t)(row * QP + ch * 4) * 4,
              Qg + (size_t)(q0 + row) * DD + ch * 4);
    }
    CPA_COMMIT();
#pragma unroll
    for (int p = 0; p < 8; p++) {            // K: 64 rows x 32 chunks
        int c = tid + p * 256;
        int row = c >> 5, ch = c & 31;
        CPA16(ksb + (uint32_t)(row * QP + ch * 4) * 4,
              Kg + (size_t)row * DD + ch * 4);
    }
    CPA_COMMIT();
#pragma unroll
    for (int p = 0; p < 8; p++) {            // V: 128 rows x 16 chunks
        int c = tid + p * 256;
        int row = c >> 4, ch = c & 15;
        CPA16(vsb + (uint32_t)(row * PP + ch * 4) * 4,
              Vg + (size_t)row * SS + ch * 4);
    }
    CPA_COMMIT();

    const int sub = lane >> 3, r8 = lane & 7;
    const int g = lane >> 2, qq = lane & 3;
    const uint32_t a_q = qsb + (uint32_t)((wid * 16 + (sub & 1) * 8 + r8) * QP + (sub >> 1) * 4) * 4;
    const uint32_t b_k = ksb + (uint32_t)(((sub >> 1) * 8 + r8) * QP + (sub & 1) * 4) * 4;
    const uint32_t a_p = smem_u32(Ps) + (uint32_t)((wid * 16 + (sub & 1) * 8 + r8) * PP + (sub >> 1) * 4) * 4;
    const uint32_t b_v = vsb + (uint32_t)(((sub >> 1) * 8 + r8) * PP + (sub & 1) * 4) * 4;

    float o[16][4];
#pragma unroll
    for (int i = 0; i < 16; i++)
#pragma unroll
        for (int j = 0; j < 4; j++) o[i][j] = 0.f;
    float m0v = -1e30f, m1v = -1e30f, l0 = 0.f, l1 = 0.f;

    const int nkt = 2 * qb + 2;
    for (int kt = 0; kt < nkt; kt++) {
        const int k0 = kt * 64;
        const bool pf = (kt + 1 < nkt);

        // [A] K(kt) (and Q on kt=0) ready
        CPA_WAIT1();
        __syncthreads();

        // S = Q K^T
        float s[8][4];
#pragma unroll
        for (int i = 0; i < 8; i++)
#pragma unroll
            for (int j = 0; j < 4; j++) s[i][j] = 0.f;
#pragma unroll
        for (int kd = 0; kd < 16; kd++) {
            uint32_t a[4];
            LDSM4(a, a_q + kd * 32);
            uint32_t bf[4][4];
#pragma unroll
            for (int nt = 0; nt < 4; nt++)
                LDSM4(bf[nt], b_k + (uint32_t)(nt * 16 * QP) * 4 + kd * 32);
#pragma unroll
            for (int nt = 0; nt < 4; nt++) {
                MMA_TF32(s[nt * 2],     a, bf[nt][0], bf[nt][1]);
                MMA_TF32(s[nt * 2 + 1], a, bf[nt][2], bf[nt][3]);
            }
        }

        // [B] all warps done reading Ks -> prefetch K(kt+1)
        __syncthreads();
        if (pf) {
            int k1 = k0 + 64;
#pragma unroll
            for (int p = 0; p < 8; p++) {
                int c = tid + p * 256;
                int row = c >> 5, ch = c & 31;
                CPA16(ksb + (uint32_t)(row * QP + ch * 4) * 4,
                      Kg + (size_t)(k1 + row) * DD + ch * 4);
            }
            CPA_COMMIT();
        }

        // causal mask (only last two tiles)
        if (kt >= 2 * qb) {
            int row0 = q0 + wid * 16 + g;
#pragma unroll
            for (int j = 0; j < 8; j++) {
                int c = k0 + j * 8 + qq * 2;
                if (c     > row0)     s[j][0] = -1e30f;
                if (c + 1 > row0)     s[j][1] = -1e30f;
                if (c     > row0 + 8) s[j][2] = -1e30f;
                if (c + 1 > row0 + 8) s[j][3] = -1e30f;
            }
        }

        // online softmax
        float tm0 = -1e30f, tm1 = -1e30f;
#pragma unroll
        for (int j = 0; j < 8; j++) {
            tm0 = fmaxf(tm0, fmaxf(s[j][0], s[j][1]));
            tm1 = fmaxf(tm1, fmaxf(s[j][2], s[j][3]));
        }
        tm0 = fmaxf(tm0, __shfl_xor_sync(0xffffffffu, tm0, 1));
        tm0 = fmaxf(tm0, __shfl_xor_sync(0xffffffffu, tm0, 2));
        tm1 = fmaxf(tm1, __shfl_xor_sync(0xffffffffu, tm1, 1));
        tm1 = fmaxf(tm1, __shfl_xor_sync(0xffffffffu, tm1, 2));
        float mn0 = fmaxf(m0v, tm0), mn1 = fmaxf(m1v, tm1);
        float al0 = __expf(m0v - mn0), al1 = __expf(m1v - mn1);
        m0v = mn0; m1v = mn1;
        float rs0 = 0.f, rs1 = 0.f;
#pragma unroll
        for (int j = 0; j < 8; j++) {
            s[j][0] = __expf(s[j][0] - mn0);
            s[j][1] = __expf(s[j][1] - mn0);
            s[j][2] = __expf(s[j][2] - mn1);
            s[j][3] = __expf(s[j][3] - mn1);
            rs0 += s[j][0] + s[j][1];
            rs1 += s[j][2] + s[j][3];
        }
        rs0 += __shfl_xor_sync(0xffffffffu, rs0, 1);
        rs0 += __shfl_xor_sync(0xffffffffu, rs0, 2);
        rs1 += __shfl_xor_sync(0xffffffffu, rs1, 1);
        rs1 += __shfl_xor_sync(0xffffffffu, rs1, 2);
        l0 = l0 * al0 + rs0;
        l1 = l1 * al1 + rs1;
#pragma unroll
        for (int nt = 0; nt < 16; nt++) {
            o[nt][0] *= al0; o[nt][1] *= al0;
            o[nt][2] *= al1; o[nt][3] *= al1;
        }

        // stage P (warp-private rows), tf32-rounded
        {
            int pr0 = (wid * 16 + g) * PP;
#pragma unroll
            for (int j = 0; j < 8; j++) {
                *(float2*)&Ps[pr0 + j * 8 + qq * 2] =
                    make_float2(to_tf32(s[j][0]), to_tf32(s[j][1]));
                *(float2*)&Ps[pr0 + 8 * PP + j * 8 + qq * 2] =
                    make_float2(to_tf32(s[j][2]), to_tf32(s[j][3]));
            }
        }
        __syncwarp();

        // [C] V(kt) ready (leave K(kt+1) in flight if prefetching)
        if (pf) { CPA_WAIT1(); } else { CPA_WAIT0(); }
        __syncthreads();

        // O += P @ V
#pragma unroll
        for (int jk = 0; jk < 8; jk++) {
            uint32_t a[4];
            LDSM4(a, a_p + jk * 32);
#pragma unroll
            for (int nt = 0; nt < 8; nt++) {
                uint32_t bf[4];
                LDSM4(bf, b_v + (uint32_t)(nt * 16 * PP) * 4 + jk * 32);
                MMA_TF32(o[nt * 2],     a, bf[0], bf[1]);
                MMA_TF32(o[nt * 2 + 1], a, bf[2], bf[3]);
            }
        }

        // [D] all warps done reading Vs -> prefetch V(kt+1)
        __syncthreads();
        if (pf) {
            int k1 = k0 + 64;
#pragma unroll
            for (int p = 0; p < 8; p++) {
                int c = tid + p * 256;
                int row = c >> 4, ch = c & 15;
                CPA16(vsb + (uint32_t)(row * PP + ch * 4) * 4,
                      Vg + (size_t)row * SS + k1 + ch * 4);
            }
            CPA_COMMIT();
        }
    }

    // normalize + tf32-round + write Y [b,s,h,d]
    float i0 = 1.f / l0, i1 = 1.f / l1;
    int row0 = q0 + wid * 16 + g;
    size_t base0 = ((size_t)b * SS + row0) * EE + h * 128;
    size_t base1 = base0 + (size_t)8 * EE;
#pragma unroll
    for (int nt = 0; nt < 16; nt++) {
        int col = nt * 8 + qq * 2;
        *(float2*)&Y[base0 + col] =
            make_float2(to_tf32(o[nt][0] * i0), to_tf32(o[nt][1] * i0));
        *(float2*)&Y[base1 + col] =
            make_float2(to_tf32(o[nt][2] * i1), to_tf32(o[nt][3] * i1));
    }
}

// ---------------- launch -----------------------------------------------------
extern "C" void kernel_launch(void* const* d_in, const int* in_sizes, int n_in,
                              void* d_out, int out_size) {
    const float* x     = (const float*)d_in[0];
    const float* w_qkv = (const float*)d_in[1];
    const float* w_out = (const float*)d_in[2];
    float* out = (float*)d_out;

    float *p_Q, *p_K, *p_Vt, *p_y;
    float2* p_rope;
    cudaGetSymbolAddress((void**)&p_Q,    g_Q);
    cudaGetSymbolAddress((void**)&p_K,    g_K);
    cudaGetSymbolAddress((void**)&p_Vt,   g_Vt);
    cudaGetSymbolAddress((void**)&p_y,    g_y);
    cudaGetSymbolAddress((void**)&p_rope, g_rope);

    cudaFuncSetAttribute(gemm_k<0,0,1>, cudaFuncAttributeMaxDynamicSharedMemorySize, GEMM_SMEM);
    cudaFuncSetAttribute(gemm_k<1,1,1>, cudaFuncAttributeMaxDynamicSharedMemorySize, GEMM_SMEM);
    cudaFuncSetAttribute(attn_mma, cudaFuncAttributeMaxDynamicSharedMemorySize, ATTN2_SMEM);

    // 0) rope table
    rope_table<<<(SS * 64) / 256, 256>>>(p_rope);

    // 1) fused: qkv GEMM (in-register tf32 rounding of x and w_qkv)
    //    + RoPE(q,k) + V transpose  → g_Q, g_K, g_Vt
    gemm_k<1,1,1><<<dim3(QKV_N / 128, MROWS / 128), 256, GEMM_SMEM>>>(
        x, w_qkv, nullptr, p_Q, p_K, p_Vt, p_rope, QKV_N, EE);
    // 2) flash attention (mma.sync tf32, cp.async pipelined)
    attn_mma<<<dim3(SS / 128, HH, BB), 256, ATTN2_SMEM>>>(p_Q, p_K, p_Vt, p_y);
    // 3) out = y @ w_out^T  (y pre-rounded; w_out rounded in-register)
    gemm_k<0,0,1><<<dim3(EE / 128, MROWS / 128), 256, GEMM_SMEM>>>(
        p_y, w_out, out, nullptr, nullptr, nullptr, nullptr, EE, EE);
}

// round 13
// speedup vs baseline: 1.0969x; 1.0969x over previous
#include <cuda_runtime.h>
#include <cuda_bf16.h>
#include <cstdint>
#include <math.h>

// Problem constants
#define BB 2
#define SS 2048
#define EE 2048
#define HH 16
#define DD 128
#define MROWS (BB * SS)          // 4096
#define QKV_N (3 * EE)           // 6144

// ---------------- scratch (device globals: allocation-free) ----------------
__device__ float g_x   [(size_t)MROWS * EE];            // tf32-rounded x
__device__ float g_wqkv[(size_t)QKV_N * EE];            // tf32-rounded w_qkv
__device__ float g_wout[(size_t)EE * EE];               // tf32-rounded w_out
__device__ float g_Q   [(size_t)BB * HH * SS * DD];     // [b,h,s,d] roped, scaled, tf32
__device__ float g_K   [(size_t)BB * HH * SS * DD];     // [b,h,s,d] roped, tf32
__device__ float g_Vt  [(size_t)BB * HH * DD * SS];     // [b,h,d,s] tf32
__device__ float g_y   [(size_t)MROWS * EE];            // [b,s,h,d], tf32-rounded
__device__ float2 g_rope[(size_t)SS * 64];              // (cos,sin) per (s, i)

// ======================= helpers ===========================================
__device__ __forceinline__ uint32_t smem_u32(const void* p) {
    uint32_t a;
    asm("{ .reg .u64 t; cvta.to.shared.u64 t, %1; cvt.u32.u64 %0, t; }"
        : "=r"(a) : "l"(p));
    return a;
}

__device__ __forceinline__ float to_tf32(float x) {
    uint32_t u;
    asm("cvt.rna.tf32.f32 %0, %1;" : "=r"(u) : "f"(x));
    return __uint_as_float(u);
}

__device__ __forceinline__ float4 round4(float4 v) {
    v.x = to_tf32(v.x); v.y = to_tf32(v.y);
    v.z = to_tf32(v.z); v.w = to_tf32(v.w);
    return v;
}

#define CPA16(dst, src) \
    asm volatile("cp.async.cg.shared.global [%0], [%1], 16;" :: "r"(dst), "l"(src))
#define CPA_COMMIT()  asm volatile("cp.async.commit_group;" ::: "memory")
#define CPA_WAIT1()   asm volatile("cp.async.wait_group 1;" ::: "memory")
#define CPA_WAIT0()   asm volatile("cp.async.wait_group 0;" ::: "memory")

#define LDSM4(r, addr)                                                        \
    asm volatile("ldmatrix.sync.aligned.m8n8.x4.shared.b16 {%0,%1,%2,%3}, [%4];" \
        : "=r"((r)[0]), "=r"((r)[1]), "=r"((r)[2]), "=r"((r)[3]) : "r"(addr))

#define MMA_TF32(c, a, b0, b1)                                                \
    asm volatile("mma.sync.aligned.m16n8k8.row.col.f32.tf32.tf32.f32 "        \
        "{%0,%1,%2,%3}, {%4,%5,%6,%7}, {%8,%9}, {%0,%1,%2,%3};"               \
        : "+f"((c)[0]), "+f"((c)[1]), "+f"((c)[2]), "+f"((c)[3])              \
        : "r"((a)[0]), "r"((a)[1]), "r"((a)[2]), "r"((a)[3]), "r"(b0), "r"(b1))

// ============ mma.sync tf32 GEMM: C[M,N] = A[M,K] @ B[N,K]^T ===============
// CTA 128x128, 256 thr / 8 warps (4m x 2n), warptile 32x64, 3-stage cp.async
// 2 CTAs per SM. FUSE=1: QKV epilogue (RoPE q/k, transpose v), FUSE=0: plain C.
#define GP 36                                // SMEM pitch (floats), %32==4
#define BOFF (128 * GP * 4)                  // B offset within stage (bytes)
#define STG_B ((128 + 128) * GP * 4)         // 36864 bytes
#define GEMM_SMEM (3 * STG_B)                // 110592 bytes

__device__ __forceinline__ void g2s_stage(const float* A, const float* B, int K,
                                          uint32_t stg, int tid) {
#pragma unroll
    for (int j = 0; j < 4; j++) {            // A: 128 rows x 8 chunks
        int cid = tid + j * 256;
        int row = cid >> 3, chk = cid & 7;
        CPA16(stg + (uint32_t)(row * GP + chk * 4) * 4,
              A + (size_t)row * K + chk * 4);
    }
#pragma unroll
    for (int j = 0; j < 4; j++) {            // B: 128 rows x 8 chunks
        int cid = tid + j * 256;
        int row = cid >> 3, chk = cid & 7;
        CPA16(stg + BOFF + (uint32_t)(row * GP + chk * 4) * 4,
              B + (size_t)row * K + chk * 4);
    }
}

template<int FUSE>
__global__ __launch_bounds__(256, 2)
void gemm_k(const float* __restrict__ A, const float* __restrict__ B,
            float* __restrict__ C,
            float* __restrict__ Qo, float* __restrict__ Ko, float* __restrict__ Vo,
            const float2* __restrict__ rt, int N, int K) {
    extern __shared__ char smem[];
    const uint32_t sbase = smem_u32(smem);
    const int tid  = threadIdx.x;
    const int wid  = tid >> 5;
    const int lane = tid & 31;
    const int wm   = wid >> 1;               // 0..3 (32 rows)
    const int wn   = wid & 1;                // 0..1 (64 cols)
    const int m0 = blockIdx.y * 128;
    const int n0 = blockIdx.x * 128;
    const int iters = K >> 5;

    const float* Ab = A + (size_t)m0 * K;
    const float* Bb = B + (size_t)n0 * K;

    float c[2][8][4];
#pragma unroll
    for (int i = 0; i < 2; i++)
#pragma unroll
        for (int j = 0; j < 8; j++)
#pragma unroll
            for (int q = 0; q < 4; q++) c[i][j][q] = 0.f;

    const int sub = lane >> 3;
    const int r8  = lane & 7;
    const uint32_t aoff = (uint32_t)((wm * 32 + (sub & 1) * 8 + r8) * GP + (sub >> 1) * 4) * 4;
    const uint32_t boff = BOFF + (uint32_t)((wn * 64 + (sub >> 1) * 8 + r8) * GP + (sub & 1) * 4) * 4;

    g2s_stage(Ab, Bb, K, sbase, tid);                   CPA_COMMIT();
    g2s_stage(Ab + 32, Bb + 32, K, sbase + STG_B, tid); CPA_COMMIT();

    for (int i = 0; i < iters; i++) {
        CPA_WAIT1();
        __syncthreads();
        if (i + 2 < iters) {
            uint32_t stg = sbase + (uint32_t)((i + 2) % 3) * STG_B;
            g2s_stage(Ab + (i + 2) * 32, Bb + (i + 2) * 32, K, stg, tid);
            CPA_COMMIT();
        }
        const uint32_t ab = sbase + (uint32_t)(i % 3) * STG_B + aoff;
        const uint32_t bb = sbase + (uint32_t)(i % 3) * STG_B + boff;

#pragma unroll
        for (int kk = 0; kk < 4; kk++) {
            uint32_t a[2][4], bf[4][4];
#pragma unroll
            for (int im = 0; im < 2; im++)
                LDSM4(a[im], ab + (uint32_t)(im * 16 * GP) * 4 + kk * 32);
#pragma unroll
            for (int nt = 0; nt < 4; nt++)
                LDSM4(bf[nt], bb + (uint32_t)(nt * 16 * GP) * 4 + kk * 32);
#pragma unroll
            for (int im = 0; im < 2; im++)
#pragma unroll
                for (int jn = 0; jn < 8; jn++)
                    MMA_TF32(c[im][jn], a[im],
                             bf[jn >> 1][(jn & 1) * 2],
                             bf[jn >> 1][(jn & 1) * 2 + 1]);
        }
    }

    const int g = lane >> 2, q = lane & 3;

    if (FUSE == 0) {
#pragma unroll
        for (int im = 0; im < 2; im++)
#pragma unroll
            for (int jn = 0; jn < 8; jn++) {
                int row = m0 + wm * 32 + im * 16 + g;
                int col = n0 + wn * 64 + jn * 8 + q * 2;
                *(float2*)&C[(size_t)row * N + col]       = make_float2(c[im][jn][0], c[im][jn][1]);
                *(float2*)&C[(size_t)(row + 8) * N + col] = make_float2(c[im][jn][2], c[im][jn][3]);
            }
    } else {
        // ---- fused QKV epilogue: stage tile, apply RoPE / transpose ----
        CPA_WAIT0();
        __syncthreads();                      // all warps done with stage SMEM
        float* Cs = (float*)smem;             // [128][132]
#pragma unroll
        for (int im = 0; im < 2; im++)
#pragma unroll
            for (int jn = 0; jn < 8; jn++) {
                int row = wm * 32 + im * 16 + g;
                int col = wn * 64 + jn * 8 + q * 2;
                *(float2*)&Cs[row * 132 + col]       = make_float2(c[im][jn][0], c[im][jn][1]);
                *(float2*)&Cs[(row + 8) * 132 + col] = make_float2(c[im][jn][2], c[im][jn][3]);
            }
        __syncthreads();

        const int hb   = n0 >> 7;             // 0..47
        const int type = hb >> 4;             // 0=q,1=k,2=v
        const int h    = hb & 15;
        const int b    = m0 >> 11;
        const int s0   = m0 & 2047;
        const size_t bh = (size_t)(b * HH + h);

        if (type < 2) {
            float* Out = (type == 0) ? Qo : Ko;
            const float scl = (type == 0) ? 0.088388347648318447f : 1.0f;
#pragma unroll
            for (int p = 0; p < 16; p++) {
                int idx = tid + p * 256;
                int row = idx >> 5, col = (idx & 31) * 4;
                int s = s0 + row;
                float4 v = *(float4*)&Cs[row * 132 + col];
                float4 w = *(float4*)&Cs[row * 132 + (col ^ 64)];
                float ov[4];
#pragma unroll
                for (int j = 0; j < 4; j++) {
                    int d = col + j;
                    float2 t = rt[s * 64 + (d & 63)];
                    float val  = (&v.x)[j];
                    float part = (&w.x)[j];
                    float r = (d < 64) ? -part : part;
                    ov[j] = to_tf32((val * t.x + r * t.y) * scl);
                }
                *(float4*)&Out[(bh * SS + s) * DD + col] =
                    make_float4(ov[0], ov[1], ov[2], ov[3]);
            }
        } else {
#pragma unroll
            for (int p = 0; p < 16; p++) {
                int idx = tid + p * 256;
                int d = idx >> 5, ch = idx & 31;
                float* vrow = Vo + (bh * DD + d) * SS + s0;
#pragma unroll
                for (int j = 0; j < 4; j++) {
                    int s = ch + j * 32;
                    vrow[s] = to_tf32(Cs[s * 132 + d]);
                }
            }
        }
    }
}

// -------- fused prologue: tf32-round x / w_qkv / w_out + rope table --------
#define X_N4   (MROWS * EE / 4)              // 2097152
#define WQ_N4  (QKV_N * EE / 4)              // 3145728
#define WO_N4  (EE * EE / 4)                 // 1048576
#define ROPE_N (SS * 64)                     // 131072
#define PREP_THREADS ((X_N4 + WQ_N4 + WO_N4 + ROPE_N))

__global__ void prep_all(const float4* __restrict__ x, const float4* __restrict__ wq,
                         const float4* __restrict__ wo,
                         float4* __restrict__ ox, float4* __restrict__ owq,
                         float4* __restrict__ owo, float2* __restrict__ rt) {
    int i = blockIdx.x * 256 + threadIdx.x;
    if (i < X_N4) { ox[i] = round4(x[i]); return; }
    i -= X_N4;
    if (i < WQ_N4) { owq[i] = round4(wq[i]); return; }
    i -= WQ_N4;
    if (i < WO_N4) { owo[i] = round4(wo[i]); return; }
    i -= WO_N4;
    int f = i & 63, s = i >> 6;
    float theta = (float)s * exp2f(-0.20762050593045998f * (float)f);
    float sn, cs;
    sincosf(theta, &sn, &cs);
    rt[i] = make_float2(cs, sn);
}

// ---------------- Flash attention via mma.sync tf32 + cp.async -------------
#define QP 132                               // pitch (floats) for Qs/Ks
#define PP 68                                // pitch for Vs/Ps
#define ATTN2_SMEM ((128 * QP + 64 * QP + 128 * PP + 128 * PP) * 4)

__global__ __launch_bounds__(256, 1)
void attn_mma(const float* __restrict__ Qg_, const float* __restrict__ Kg_,
              const float* __restrict__ Vt_, float* __restrict__ Y) {
    extern __shared__ float sm[];
    float* Qs = sm;                          // [128][QP]  rows=qrow cols=d
    float* Ks = Qs + 128 * QP;               // [64][QP]   rows=kcol cols=d
    float* Vs = Ks + 64 * QP;                // [128][PP]  rows=d    cols=kcol
    float* Ps = Vs + 128 * PP;               // [128][PP]  rows=qrow cols=kcol

    const int tid  = threadIdx.x;
    const int wid  = tid >> 5;
    const int lane = tid & 31;
    const int qb = gridDim.x - 1 - blockIdx.x;   // heavy tiles first
    const int h  = blockIdx.y;
    const int b  = blockIdx.z;
    const int q0 = qb * 128;

    const size_t bh = (size_t)(b * HH + h);
    const float* Qg = Qg_ + bh * SS * DD;    // [s][d] (scaled, tf32)
    const float* Kg = Kg_ + bh * SS * DD;    // [s][d] (tf32)
    const float* Vg = Vt_ + bh * DD * SS;    // [d][s] (tf32)

    const uint32_t qsb = smem_u32(Qs);
    const uint32_t ksb = smem_u32(Ks);
    const uint32_t vsb = smem_u32(Vs);

    // prologue: async Q tile (group 1), K(0) (group 2), V(0) (group 3)
#pragma unroll
    for (int p = 0; p < 16; p++) {           // Q: 128 rows x 32 chunks
        int c = tid + p * 256;
        int row = c >> 5, ch = c & 31;
        CPA16(qsb + (uint32_t)(row * QP + ch * 4) * 4,
              Qg + (size_t)(q0 + row) * DD + ch * 4);
    }
    CPA_COMMIT();
#pragma unroll
    for (int p = 0; p < 8; p++) {            // K: 64 rows x 32 chunks
        int c = tid + p * 256;
        int row = c >> 5, ch = c & 31;
        CPA16(ksb + (uint32_t)(row * QP + ch * 4) * 4,
              Kg + (size_t)row * DD + ch * 4);
    }
    CPA_COMMIT();
#pragma unroll
    for (int p = 0; p < 8; p++) {            // V: 128 rows x 16 chunks
        int c = tid + p * 256;
        int row = c >> 4, ch = c & 15;
        CPA16(vsb + (uint32_t)(row * PP + ch * 4) * 4,
              Vg + (size_t)row * SS + ch * 4);
    }
    CPA_COMMIT();

    const int sub = lane >> 3, r8 = lane & 7;
    const int g = lane >> 2, qq = lane & 3;
    const uint32_t a_q = qsb + (uint32_t)((wid * 16 + (sub & 1) * 8 + r8) * QP + (sub >> 1) * 4) * 4;
    const uint32_t b_k = ksb + (uint32_t)(((sub >> 1) * 8 + r8) * QP + (sub & 1) * 4) * 4;
    const uint32_t a_p = smem_u32(Ps) + (uint32_t)((wid * 16 + (sub & 1) * 8 + r8) * PP + (sub >> 1) * 4) * 4;
    const uint32_t b_v = vsb + (uint32_t)(((sub >> 1) * 8 + r8) * PP + (sub & 1) * 4) * 4;

    float o[16][4];
#pragma unroll
    for (int i = 0; i < 16; i++)
#pragma unroll
        for (int j = 0; j < 4; j++) o[i][j] = 0.f;
    float m0v = -1e30f, m1v = -1e30f, l0 = 0.f, l1 = 0.f;

    const int nkt = 2 * qb + 2;
    for (int kt = 0; kt < nkt; kt++) {
        const int k0 = kt * 64;
        const bool pf = (kt + 1 < nkt);

        // [A] K(kt) (and Q on kt=0) ready
        CPA_WAIT1();
        __syncthreads();

        // S = Q K^T
        float s[8][4];
#pragma unroll
        for (int i = 0; i < 8; i++)
#pragma unroll
            for (int j = 0; j < 4; j++) s[i][j] = 0.f;
#pragma unroll
        for (int kd = 0; kd < 16; kd++) {
            uint32_t a[4];
            LDSM4(a, a_q + kd * 32);
            uint32_t bf[4][4];
#pragma unroll
            for (int nt = 0; nt < 4; nt++)
                LDSM4(bf[nt], b_k + (uint32_t)(nt * 16 * QP) * 4 + kd * 32);
#pragma unroll
            for (int nt = 0; nt < 4; nt++) {
                MMA_TF32(s[nt * 2],     a, bf[nt][0], bf[nt][1]);
                MMA_TF32(s[nt * 2 + 1], a, bf[nt][2], bf[nt][3]);
            }
        }

        // [B] all warps done reading Ks -> prefetch K(kt+1)
        __syncthreads();
        if (pf) {
            int k1 = k0 + 64;
#pragma unroll
            for (int p = 0; p < 8; p++) {
                int c = tid + p * 256;
                int row = c >> 5, ch = c & 31;
                CPA16(ksb + (uint32_t)(row * QP + ch * 4) * 4,
                      Kg + (size_t)(k1 + row) * DD + ch * 4);
            }
            CPA_COMMIT();
        }

        // causal mask (only last two tiles)
        if (kt >= 2 * qb) {
            int row0 = q0 + wid * 16 + g;
#pragma unroll
            for (int j = 0; j < 8; j++) {
                int c = k0 + j * 8 + qq * 2;
                if (c     > row0)     s[j][0] = -1e30f;
                if (c + 1 > row0)     s[j][1] = -1e30f;
                if (c     > row0 + 8) s[j][2] = -1e30f;
                if (c + 1 > row0 + 8) s[j][3] = -1e30f;
            }
        }

        // online softmax
        float tm0 = -1e30f, tm1 = -1e30f;
#pragma unroll
        for (int j = 0; j < 8; j++) {
            tm0 = fmaxf(tm0, fmaxf(s[j][0], s[j][1]));
            tm1 = fmaxf(tm1, fmaxf(s[j][2], s[j][3]));
        }
        tm0 = fmaxf(tm0, __shfl_xor_sync(0xffffffffu, tm0, 1));
        tm0 = fmaxf(tm0, __shfl_xor_sync(0xffffffffu, tm0, 2));
        tm1 = fmaxf(tm1, __shfl_xor_sync(0xffffffffu, tm1, 1));
        tm1 = fmaxf(tm1, __shfl_xor_sync(0xffffffffu, tm1, 2));
        float mn0 = fmaxf(m0v, tm0), mn1 = fmaxf(m1v, tm1);
        float al0 = __expf(m0v - mn0), al1 = __expf(m1v - mn1);
        m0v = mn0; m1v = mn1;
        float rs0 = 0.f, rs1 = 0.f;
#pragma unroll
        for (int j = 0; j < 8; j++) {
            s[j][0] = __expf(s[j][0] - mn0);
            s[j][1] = __expf(s[j][1] - mn0);
            s[j][2] = __expf(s[j][2] - mn1);
            s[j][3] = __expf(s[j][3] - mn1);
            rs0 += s[j][0] + s[j][1];
            rs1 += s[j][2] + s[j][3];
        }
        rs0 += __shfl_xor_sync(0xffffffffu, rs0, 1);
        rs0 += __shfl_xor_sync(0xffffffffu, rs0, 2);
        rs1 += __shfl_xor_sync(0xffffffffu, rs1, 1);
        rs1 += __shfl_xor_sync(0xffffffffu, rs1, 2);
        l0 = l0 * al0 + rs0;
        l1 = l1 * al1 + rs1;
#pragma unroll
        for (int nt = 0; nt < 16; nt++) {
            o[nt][0] *= al0; o[nt][1] *= al0;
            o[nt][2] *= al1; o[nt][3] *= al1;
        }

        // stage P (warp-private rows), tf32-rounded
        {
            int pr0 = (wid * 16 + g) * PP;
#pragma unroll
            for (int j = 0; j < 8; j++) {
                *(float2*)&Ps[pr0 + j * 8 + qq * 2] =
                    make_float2(to_tf32(s[j][0]), to_tf32(s[j][1]));
                *(float2*)&Ps[pr0 + 8 * PP + j * 8 + qq * 2] =
                    make_float2(to_tf32(s[j][2]), to_tf32(s[j][3]));
            }
        }
        __syncwarp();

        // [C] V(kt) ready (leave K(kt+1) in flight if prefetching)
        if (pf) { CPA_WAIT1(); } else { CPA_WAIT0(); }
        __syncthreads();

        // O += P @ V
#pragma unroll
        for (int jk = 0; jk < 8; jk++) {
            uint32_t a[4];
            LDSM4(a, a_p + jk * 32);
#pragma unroll
            for (int nt = 0; nt < 8; nt++) {
                uint32_t bf[4];
                LDSM4(bf, b_v + (uint32_t)(nt * 16 * PP) * 4 + jk * 32);
                MMA_TF32(o[nt * 2],     a, bf[0], bf[1]);
                MMA_TF32(o[nt * 2 + 1], a, bf[2], bf[3]);
            }
        }

        // [D] all warps done reading Vs -> prefetch V(kt+1)
        __syncthreads();
        if (pf) {
            int k1 = k0 + 64;
#pragma unroll
            for (int p = 0; p < 8; p++) {
                int c = tid + p * 256;
                int row = c >> 4, ch = c & 15;
                CPA16(vsb + (uint32_t)(row * PP + ch * 4) * 4,
                      Vg + (size_t)row * SS + k1 + ch * 4);
            }
            CPA_COMMIT();
        }
    }

    // normalize + tf32-round + write Y [b,s,h,d]
    float i0 = 1.f / l0, i1 = 1.f / l1;
    int row0 = q0 + wid * 16 + g;
    size_t base0 = ((size_t)b * SS + row0) * EE + h * 128;
    size_t base1 = base0 + (size_t)8 * EE;
#pragma unroll
    for (int nt = 0; nt < 16; nt++) {
        int col = nt * 8 + qq * 2;
        *(float2*)&Y[base0 + col] =
            make_float2(to_tf32(o[nt][0] * i0), to_tf32(o[nt][1] * i0));
        *(float2*)&Y[base1 + col] =
            make_float2(to_tf32(o[nt][2] * i1), to_tf32(o[nt][3] * i1));
    }
}

// ---------------- launch -----------------------------------------------------
extern "C" void kernel_launch(void* const* d_in, const int* in_sizes, int n_in,
                              void* d_out, int out_size) {
    const float* x     = (const float*)d_in[0];
    const float* w_qkv = (const float*)d_in[1];
    const float* w_out = (const float*)d_in[2];
    float* out = (float*)d_out;

    float *p_x, *p_wqkv, *p_wout, *p_Q, *p_K, *p_Vt, *p_y;
    float2* p_rope;
    cudaGetSymbolAddress((void**)&p_x,    g_x);
    cudaGetSymbolAddress((void**)&p_wqkv, g_wqkv);
    cudaGetSymbolAddress((void**)&p_wout, g_wout);
    cudaGetSymbolAddress((void**)&p_Q,    g_Q);
    cudaGetSymbolAddress((void**)&p_K,    g_K);
    cudaGetSymbolAddress((void**)&p_Vt,   g_Vt);
    cudaGetSymbolAddress((void**)&p_y,    g_y);
    cudaGetSymbolAddress((void**)&p_rope, g_rope);

    cudaFuncSetAttribute(gemm_k<0>, cudaFuncAttributeMaxDynamicSharedMemorySize, GEMM_SMEM);
    cudaFuncSetAttribute(gemm_k<1>, cudaFuncAttributeMaxDynamicSharedMemorySize, GEMM_SMEM);
    cudaFuncSetAttribute(attn_mma, cudaFuncAttributeMaxDynamicSharedMemorySize, ATTN2_SMEM);

    // 0) single fused prologue: round x / w_qkv / w_out to tf32 + rope table
    prep_all<<<PREP_THREADS / 256, 256>>>(
        (const float4*)x, (const float4*)w_qkv, (const float4*)w_out,
        (float4*)p_x, (float4*)p_wqkv, (float4*)p_wout, p_rope);

    // 1) fused: qkv GEMM + RoPE(q,k) + V transpose  → g_Q, g_K, g_Vt
    gemm_k<1><<<dim3(QKV_N / 128, MROWS / 128), 256, GEMM_SMEM>>>(
        p_x, p_wqkv, nullptr, p_Q, p_K, p_Vt, p_rope, QKV_N, EE);
    // 2) flash attention (mma.sync tf32, cp.async pipelined)
    attn_mma<<<dim3(SS / 128, HH, BB), 256, ATTN2_SMEM>>>(p_Q, p_K, p_Vt, p_y);
    // 3) out = y @ w_out^T
    gemm_k<0><<<dim3(EE / 128, MROWS / 128), 256, GEMM_SMEM>>>(
        p_y, p_wout, out, nullptr, nullptr, nullptr, nullptr, EE, EE);
}

// round 14
// speedup vs baseline: 1.1671x; 1.0640x over previous
#include <cuda_runtime.h>
#include <cuda_bf16.h>
#include <cstdint>
#include <math.h>

// Problem constants
#define BB 2
#define SS 2048
#define EE 2048
#define HH 16
#define DD 128
#define MROWS (BB * SS)          // 4096
#define QKV_N (3 * EE)           // 6144

// ---------------- scratch (device globals: allocation-free) ----------------
__device__ float g_x   [(size_t)MROWS * EE];            // tf32-rounded x
__device__ float g_wqkv[(size_t)QKV_N * EE];            // tf32-rounded w_qkv
__device__ float g_wout[(size_t)EE * EE];               // tf32-rounded w_out
__device__ float g_Q   [(size_t)BB * HH * SS * DD];     // [b,h,s,d] roped, scaled, tf32
__device__ float g_K   [(size_t)BB * HH * SS * DD];     // [b,h,s,d] roped, tf32
__device__ float g_Vt  [(size_t)BB * HH * DD * SS];     // [b,h,d,s] tf32
__device__ float g_y   [(size_t)MROWS * EE];            // [b,s,h,d], tf32-rounded
__device__ float2 g_rope[(size_t)SS * 64];              // (cos,sin) per (s, i)

// ======================= helpers ===========================================
__device__ __forceinline__ uint32_t smem_u32(const void* p) {
    uint32_t a;
    asm("{ .reg .u64 t; cvta.to.shared.u64 t, %1; cvt.u32.u64 %0, t; }"
        : "=r"(a) : "l"(p));
    return a;
}

__device__ __forceinline__ float to_tf32(float x) {
    uint32_t u;
    asm("cvt.rna.tf32.f32 %0, %1;" : "=r"(u) : "f"(x));
    return __uint_as_float(u);
}

__device__ __forceinline__ float4 round4(float4 v) {
    v.x = to_tf32(v.x); v.y = to_tf32(v.y);
    v.z = to_tf32(v.z); v.w = to_tf32(v.w);
    return v;
}

#define CPA16(dst, src) \
    asm volatile("cp.async.cg.shared.global [%0], [%1], 16;" :: "r"(dst), "l"(src))
#define CPA_COMMIT()  asm volatile("cp.async.commit_group;" ::: "memory")
#define CPA_WAIT1()   asm volatile("cp.async.wait_group 1;" ::: "memory")
#define CPA_WAIT0()   asm volatile("cp.async.wait_group 0;" ::: "memory")

#define LDSM4(r, addr)                                                        \
    asm volatile("ldmatrix.sync.aligned.m8n8.x4.shared.b16 {%0,%1,%2,%3}, [%4];" \
        : "=r"((r)[0]), "=r"((r)[1]), "=r"((r)[2]), "=r"((r)[3]) : "r"(addr))

#define MMA_TF32(c, a, b0, b1)                                                \
    asm volatile("mma.sync.aligned.m16n8k8.row.col.f32.tf32.tf32.f32 "        \
        "{%0,%1,%2,%3}, {%4,%5,%6,%7}, {%8,%9}, {%0,%1,%2,%3};"               \
        : "+f"((c)[0]), "+f"((c)[1]), "+f"((c)[2]), "+f"((c)[3])              \
        : "r"((a)[0]), "r"((a)[1]), "r"((a)[2]), "r"((a)[3]), "r"(b0), "r"(b1))

// ============ mma.sync tf32 GEMM: C[M,N] = A[M,K] @ B[N,K]^T ===============
// CTA 128x128, 256 thr / 8 warps (4m x 2n), warptile 32x64, 3-stage cp.async
// 2 CTAs per SM. FUSE=1: QKV epilogue (RoPE q/k, transpose v), FUSE=0: plain C.
#define GP 36                                // SMEM pitch (floats), %32==4
#define BOFF (128 * GP * 4)                  // B offset within stage (bytes)
#define STG_B ((128 + 128) * GP * 4)         // 36864 bytes
#define GEMM_SMEM (3 * STG_B)                // 110592 bytes
#define CP 136                               // epilogue staging pitch (floats)

__device__ __forceinline__ void g2s_stage(const float* A, const float* B, int K,
                                          uint32_t stg, int tid) {
#pragma unroll
    for (int j = 0; j < 4; j++) {            // A: 128 rows x 8 chunks
        int cid = tid + j * 256;
        int row = cid >> 3, chk = cid & 7;
        CPA16(stg + (uint32_t)(row * GP + chk * 4) * 4,
              A + (size_t)row * K + chk * 4);
    }
#pragma unroll
    for (int j = 0; j < 4; j++) {            // B: 128 rows x 8 chunks
        int cid = tid + j * 256;
        int row = cid >> 3, chk = cid & 7;
        CPA16(stg + BOFF + (uint32_t)(row * GP + chk * 4) * 4,
              B + (size_t)row * K + chk * 4);
    }
}

template<int FUSE>
__global__ __launch_bounds__(256, 2)
void gemm_k(const float* __restrict__ A, const float* __restrict__ B,
            float* __restrict__ C,
            float* __restrict__ Qo, float* __restrict__ Ko, float* __restrict__ Vo,
            const float2* __restrict__ rt, int N, int K) {
    extern __shared__ char smem[];
    const uint32_t sbase = smem_u32(smem);
    const int tid  = threadIdx.x;
    const int wid  = tid >> 5;
    const int lane = tid & 31;
    const int wm   = wid >> 1;               // 0..3 (32 rows)
    const int wn   = wid & 1;                // 0..1 (64 cols)
    const int m0 = blockIdx.y * 128;
    const int n0 = blockIdx.x * 128;
    const int iters = K >> 5;

    const float* Ab = A + (size_t)m0 * K;
    const float* Bb = B + (size_t)n0 * K;

    float c[2][8][4];
#pragma unroll
    for (int i = 0; i < 2; i++)
#pragma unroll
        for (int j = 0; j < 8; j++)
#pragma unroll
            for (int q = 0; q < 4; q++) c[i][j][q] = 0.f;

    const int sub = lane >> 3;
    const int r8  = lane & 7;
    const uint32_t aoff = (uint32_t)((wm * 32 + (sub & 1) * 8 + r8) * GP + (sub >> 1) * 4) * 4;
    const uint32_t boff = BOFF + (uint32_t)((wn * 64 + (sub >> 1) * 8 + r8) * GP + (sub & 1) * 4) * 4;

    g2s_stage(Ab, Bb, K, sbase, tid);                   CPA_COMMIT();
    g2s_stage(Ab + 32, Bb + 32, K, sbase + STG_B, tid); CPA_COMMIT();

    for (int i = 0; i < iters; i++) {
        CPA_WAIT1();
        __syncthreads();
        if (i + 2 < iters) {
            uint32_t stg = sbase + (uint32_t)((i + 2) % 3) * STG_B;
            g2s_stage(Ab + (i + 2) * 32, Bb + (i + 2) * 32, K, stg, tid);
            CPA_COMMIT();
        }
        const uint32_t ab = sbase + (uint32_t)(i % 3) * STG_B + aoff;
        const uint32_t bb = sbase + (uint32_t)(i % 3) * STG_B + boff;

#pragma unroll
        for (int kk = 0; kk < 4; kk++) {
            uint32_t a[2][4], bf[4][4];
#pragma unroll
            for (int im = 0; im < 2; im++)
                LDSM4(a[im], ab + (uint32_t)(im * 16 * GP) * 4 + kk * 32);
#pragma unroll
            for (int nt = 0; nt < 4; nt++)
                LDSM4(bf[nt], bb + (uint32_t)(nt * 16 * GP) * 4 + kk * 32);
#pragma unroll
            for (int im = 0; im < 2; im++)
#pragma unroll
                for (int jn = 0; jn < 8; jn++)
                    MMA_TF32(c[im][jn], a[im],
                             bf[jn >> 1][(jn & 1) * 2],
                             bf[jn >> 1][(jn & 1) * 2 + 1]);
        }
    }

    const int g = lane >> 2, q = lane & 3;

    if (FUSE == 0) {
#pragma unroll
        for (int im = 0; im < 2; im++)
#pragma unroll
            for (int jn = 0; jn < 8; jn++) {
                int row = m0 + wm * 32 + im * 16 + g;
                int col = n0 + wn * 64 + jn * 8 + q * 2;
                *(float2*)&C[(size_t)row * N + col]       = make_float2(c[im][jn][0], c[im][jn][1]);
                *(float2*)&C[(size_t)(row + 8) * N + col] = make_float2(c[im][jn][2], c[im][jn][3]);
            }
    } else {
        // ---- fused QKV epilogue: stage tile, apply RoPE / transpose ----
        CPA_WAIT0();
        __syncthreads();                      // all warps done with stage SMEM
        float* Cs = (float*)smem;             // [128][CP]
#pragma unroll
        for (int im = 0; im < 2; im++)
#pragma unroll
            for (int jn = 0; jn < 8; jn++) {
                int row = wm * 32 + im * 16 + g;
                int col = wn * 64 + jn * 8 + q * 2;
                *(float2*)&Cs[row * CP + col]       = make_float2(c[im][jn][0], c[im][jn][1]);
                *(float2*)&Cs[(row + 8) * CP + col] = make_float2(c[im][jn][2], c[im][jn][3]);
            }
        __syncthreads();

        const int hb   = n0 >> 7;             // 0..47
        const int type = hb >> 4;             // 0=q,1=k,2=v
        const int h    = hb & 15;
        const int b    = m0 >> 11;
        const int s0   = m0 & 2047;
        const size_t bh = (size_t)(b * HH + h);

        if (type < 2) {
            float* Out = (type == 0) ? Qo : Ko;
            const float scl = (type == 0) ? 0.088388347648318447f : 1.0f;
#pragma unroll
            for (int p = 0; p < 16; p++) {
                int idx = tid + p * 256;
                int row = idx >> 5, col = (idx & 31) * 4;
                int s = s0 + row;
                float4 v = *(float4*)&Cs[row * CP + col];
                float4 w = *(float4*)&Cs[row * CP + (col ^ 64)];
                float ov[4];
#pragma unroll
                for (int j = 0; j < 4; j++) {
                    int d = col + j;
                    float2 t = rt[s * 64 + (d & 63)];
                    float val  = (&v.x)[j];
                    float part = (&w.x)[j];
                    float r = (d < 64) ? -part : part;
                    ov[j] = to_tf32((val * t.x + r * t.y) * scl);
                }
                *(float4*)&Out[(bh * SS + s) * DD + col] =
                    make_float4(ov[0], ov[1], ov[2], ov[3]);
            }
        } else {
#pragma unroll
            for (int p = 0; p < 16; p++) {
                int idx = tid + p * 256;
                int d = idx >> 5, ch = idx & 31;
                float* vrow = Vo + (bh * DD + d) * SS + s0;
#pragma unroll
                for (int j = 0; j < 4; j++) {
                    int s = ch + j * 32;
                    vrow[s] = to_tf32(Cs[s * CP + d]);
                }
            }
        }
    }
}

// -------- fused prologue: tf32-round x / w_qkv / w_out + rope table --------
#define X_N4   (MROWS * EE / 4)              // 2097152
#define WQ_N4  (QKV_N * EE / 4)              // 3145728
#define WO_N4  (EE * EE / 4)                 // 1048576
#define ROPE_N (SS * 64)                     // 131072
#define PREP_THREADS ((X_N4 + WQ_N4 + WO_N4 + ROPE_N))

__global__ void prep_all(const float4* __restrict__ x, const float4* __restrict__ wq,
                         const float4* __restrict__ wo,
                         float4* __restrict__ ox, float4* __restrict__ owq,
                         float4* __restrict__ owo, float2* __restrict__ rt) {
    int i = blockIdx.x * 256 + threadIdx.x;
    if (i < X_N4) { ox[i] = round4(x[i]); return; }
    i -= X_N4;
    if (i < WQ_N4) { owq[i] = round4(wq[i]); return; }
    i -= WQ_N4;
    if (i < WO_N4) { owo[i] = round4(wo[i]); return; }
    i -= WO_N4;
    int f = i & 63, s = i >> 6;
    float theta = (float)s * exp2f(-0.20762050593045998f * (float)f);
    float sn, cs;
    sincosf(theta, &sn, &cs);
    rt[i] = make_float2(cs, sn);
}

// ---------------- Flash attention via mma.sync tf32 + cp.async -------------
// 1D grid of 512 CTAs, globally sorted heavy-first (qb=15 tiles launch first).
#define QP 132                               // pitch (floats) for Qs/Ks
#define PP 68                                // pitch for Vs/Ps
#define ATTN2_SMEM ((128 * QP + 64 * QP + 128 * PP + 128 * PP) * 4)

__global__ __launch_bounds__(256, 1)
void attn_mma(const float* __restrict__ Qg_, const float* __restrict__ Kg_,
              const float* __restrict__ Vt_, float* __restrict__ Y) {
    extern __shared__ float sm[];
    float* Qs = sm;                          // [128][QP]  rows=qrow cols=d
    float* Ks = Qs + 128 * QP;               // [64][QP]   rows=kcol cols=d
    float* Vs = Ks + 64 * QP;                // [128][PP]  rows=d    cols=kcol
    float* Ps = Vs + 128 * PP;               // [128][PP]  rows=qrow cols=kcol

    const int tid  = threadIdx.x;
    const int wid  = tid >> 5;
    const int lane = tid & 31;
    const int flat = blockIdx.x;                 // 0..511
    const int qb = (SS / 128 - 1) - (flat >> 5); // heavy qb first, all (h,b)
    const int hb = flat & 31;
    const int h  = hb & 15;
    const int b  = hb >> 4;
    const int q0 = qb * 128;

    const size_t bh = (size_t)(b * HH + h);
    const float* Qg = Qg_ + bh * SS * DD;    // [s][d] (scaled, tf32)
    const float* Kg = Kg_ + bh * SS * DD;    // [s][d] (tf32)
    const float* Vg = Vt_ + bh * DD * SS;    // [d][s] (tf32)

    const uint32_t qsb = smem_u32(Qs);
    const uint32_t ksb = smem_u32(Ks);
    const uint32_t vsb = smem_u32(Vs);

    // prologue: async Q tile (group 1), K(0) (group 2), V(0) (group 3)
#pragma unroll
    for (int p = 0; p < 16; p++) {           // Q: 128 rows x 32 chunks
        int c = tid + p * 256;
        int row = c >> 5, ch = c & 31;
        CPA16(qsb + (uint32_t)(row * QP + ch * 4) * 4,
              Qg + (size_t)(q0 + row) * DD + ch * 4);
    }
    CPA_COMMIT();
#pragma unroll
    for (int p = 0; p < 8; p++) {            // K: 64 rows x 32 chunks
        int c = tid + p * 256;
        int row = c >> 5, ch = c & 31;
        CPA16(ksb + (uint32_t)(row * QP + ch * 4) * 4,
              Kg + (size_t)row * DD + ch * 4);
    }
    CPA_COMMIT();
#pragma unroll
    for (int p = 0; p < 8; p++) {            // V: 128 rows x 16 chunks
        int c = tid + p * 256;
        int row = c >> 4, ch = c & 15;
        CPA16(vsb + (uint32_t)(row * PP + ch * 4) * 4,
              Vg + (size_t)row * SS + ch * 4);
    }
    CPA_COMMIT();

    const int sub = lane >> 3, r8 = lane & 7;
    const int g = lane >> 2, qq = lane & 3;
    const uint32_t a_q = qsb + (uint32_t)((wid * 16 + (sub & 1) * 8 + r8) * QP + (sub >> 1) * 4) * 4;
    const uint32_t b_k = ksb + (uint32_t)(((sub >> 1) * 8 + r8) * QP + (sub & 1) * 4) * 4;
    const uint32_t a_p = smem_u32(Ps) + (uint32_t)((wid * 16 + (sub & 1) * 8 + r8) * PP + (sub >> 1) * 4) * 4;
    const uint32_t b_v = vsb + (uint32_t)(((sub >> 1) * 8 + r8) * PP + (sub & 1) * 4) * 4;

    float o[16][4];
#pragma unroll
    for (int i = 0; i < 16; i++)
#pragma unroll
        for (int j = 0; j < 4; j++) o[i][j] = 0.f;
    float m0v = -1e30f, m1v = -1e30f, l0 = 0.f, l1 = 0.f;

    const int nkt = 2 * qb + 2;
    for (int kt = 0; kt < nkt; kt++) {
        const int k0 = kt * 64;
        const bool pf = (kt + 1 < nkt);

        // [A] K(kt) (and Q on kt=0) ready
        CPA_WAIT1();
        __syncthreads();

        // S = Q K^T
        float s[8][4];
#pragma unroll
        for (int i = 0; i < 8; i++)
#pragma unroll
            for (int j = 0; j < 4; j++) s[i][j] = 0.f;
#pragma unroll
        for (int kd = 0; kd < 16; kd++) {
            uint32_t a[4];
            LDSM4(a, a_q + kd * 32);
            uint32_t bf[4][4];
#pragma unroll
            for (int nt = 0; nt < 4; nt++)
                LDSM4(bf[nt], b_k + (uint32_t)(nt * 16 * QP) * 4 + kd * 32);
#pragma unroll
            for (int nt = 0; nt < 4; nt++) {
                MMA_TF32(s[nt * 2],     a, bf[nt][0], bf[nt][1]);
                MMA_TF32(s[nt * 2 + 1], a, bf[nt][2], bf[nt][3]);
            }
        }

        // [B] all warps done reading Ks -> prefetch K(kt+1)
        __syncthreads();
        if (pf) {
            int k1 = k0 + 64;
#pragma unroll
            for (int p = 0; p < 8; p++) {
                int c = tid + p * 256;
                int row = c >> 5, ch = c & 31;
                CPA16(ksb + (uint32_t)(row * QP + ch * 4) * 4,
                      Kg + (size_t)(k1 + row) * DD + ch * 4);
            }
            CPA_COMMIT();
        }

        // causal mask (only last two tiles)
        if (kt >= 2 * qb) {
            int row0 = q0 + wid * 16 + g;
#pragma unroll
            for (int j = 0; j < 8; j++) {
                int c = k0 + j * 8 + qq * 2;
                if (c     > row0)     s[j][0] = -1e30f;
                if (c + 1 > row0)     s[j][1] = -1e30f;
                if (c     > row0 + 8) s[j][2] = -1e30f;
                if (c + 1 > row0 + 8) s[j][3] = -1e30f;
            }
        }

        // online softmax
        float tm0 = -1e30f, tm1 = -1e30f;
#pragma unroll
        for (int j = 0; j < 8; j++) {
            tm0 = fmaxf(tm0, fmaxf(s[j][0], s[j][1]));
            tm1 = fmaxf(tm1, fmaxf(s[j][2], s[j][3]));
        }
        tm0 = fmaxf(tm0, __shfl_xor_sync(0xffffffffu, tm0, 1));
        tm0 = fmaxf(tm0, __shfl_xor_sync(0xffffffffu, tm0, 2));
        tm1 = fmaxf(tm1, __shfl_xor_sync(0xffffffffu, tm1, 1));
        tm1 = fmaxf(tm1, __shfl_xor_sync(0xffffffffu, tm1, 2));
        float mn0 = fmaxf(m0v, tm0), mn1 = fmaxf(m1v, tm1);
        float al0 = __expf(m0v - mn0), al1 = __expf(m1v - mn1);
        m0v = mn0; m1v = mn1;
        float rs0 = 0.f, rs1 = 0.f;
#pragma unroll
        for (int j = 0; j < 8; j++) {
            s[j][0] = __expf(s[j][0] - mn0);
            s[j][1] = __expf(s[j][1] - mn0);
            s[j][2] = __expf(s[j][2] - mn1);
            s[j][3] = __expf(s[j][3] - mn1);
            rs0 += s[j][0] + s[j][1];
            rs1 += s[j][2] + s[j][3];
        }
        rs0 += __shfl_xor_sync(0xffffffffu, rs0, 1);
        rs0 += __shfl_xor_sync(0xffffffffu, rs0, 2);
        rs1 += __shfl_xor_sync(0xffffffffu, rs1, 1);
        rs1 += __shfl_xor_sync(0xffffffffu, rs1, 2);
        l0 = l0 * al0 + rs0;
        l1 = l1 * al1 + rs1;
#pragma unroll
        for (int nt = 0; nt < 16; nt++) {
            o[nt][0] *= al0; o[nt][1] *= al0;
            o[nt][2] *= al1; o[nt][3] *= al1;
        }

        // stage P (warp-private rows), tf32-rounded
        {
            int pr0 = (wid * 16 + g) * PP;
#pragma unroll
            for (int j = 0; j < 8; j++) {
                *(float2*)&Ps[pr0 + j * 8 + qq * 2] =
                    make_float2(to_tf32(s[j][0]), to_tf32(s[j][1]));
                *(float2*)&Ps[pr0 + 8 * PP + j * 8 + qq * 2] =
                    make_float2(to_tf32(s[j][2]), to_tf32(s[j][3]));
            }
        }
        __syncwarp();

        // [C] V(kt) ready (leave K(kt+1) in flight if prefetching)
        if (pf) { CPA_WAIT1(); } else { CPA_WAIT0(); }
        __syncthreads();

        // O += P @ V
#pragma unroll
        for (int jk = 0; jk < 8; jk++) {
            uint32_t a[4];
            LDSM4(a, a_p + jk * 32);
#pragma unroll
            for (int nt = 0; nt < 8; nt++) {
                uint32_t bf[4];
                LDSM4(bf, b_v + (uint32_t)(nt * 16 * PP) * 4 + jk * 32);
                MMA_TF32(o[nt * 2],     a, bf[0], bf[1]);
                MMA_TF32(o[nt * 2 + 1], a, bf[2], bf[3]);
            }
        }

        // [D] all warps done reading Vs -> prefetch V(kt+1)
        __syncthreads();
        if (pf) {
            int k1 = k0 + 64;
#pragma unroll
            for (int p = 0; p < 8; p++) {
                int c = tid + p * 256;
                int row = c >> 4, ch = c & 15;
                CPA16(vsb + (uint32_t)(row * PP + ch * 4) * 4,
                      Vg + (size_t)row * SS + k1 + ch * 4);
            }
            CPA_COMMIT();
        }
    }

    // normalize + tf32-round + write Y [b,s,h,d]
    float i0 = 1.f / l0, i1 = 1.f / l1;
    int row0 = q0 + wid * 16 + g;
    size_t base0 = ((size_t)b * SS + row0) * EE + h * 128;
    size_t base1 = base0 + (size_t)8 * EE;
#pragma unroll
    for (int nt = 0; nt < 16; nt++) {
        int col = nt * 8 + qq * 2;
        *(float2*)&Y[base0 + col] =
            make_float2(to_tf32(o[nt][0] * i0), to_tf32(o[nt][1] * i0));
        *(float2*)&Y[base1 + col] =
            make_float2(to_tf32(o[nt][2] * i1), to_tf32(o[nt][3] * i1));
    }
}

// ---------------- launch -----------------------------------------------------
extern "C" void kernel_launch(void* const* d_in, const int* in_sizes, int n_in,
                              void* d_out, int out_size) {
    const float* x     = (const float*)d_in[0];
    const float* w_qkv = (const float*)d_in[1];
    const float* w_out = (const float*)d_in[2];
    float* out = (float*)d_out;

    float *p_x, *p_wqkv, *p_wout, *p_Q, *p_K, *p_Vt, *p_y;
    float2* p_rope;
    cudaGetSymbolAddress((void**)&p_x,    g_x);
    cudaGetSymbolAddress((void**)&p_wqkv, g_wqkv);
    cudaGetSymbolAddress((void**)&p_wout, g_wout);
    cudaGetSymbolAddress((void**)&p_Q,    g_Q);
    cudaGetSymbolAddress((void**)&p_K,    g_K);
    cudaGetSymbolAddress((void**)&p_Vt,   g_Vt);
    cudaGetSymbolAddress((void**)&p_y,    g_y);
    cudaGetSymbolAddress((void**)&p_rope, g_rope);

    cudaFuncSetAttribute(gemm_k<0>, cudaFuncAttributeMaxDynamicSharedMemorySize, GEMM_SMEM);
    cudaFuncSetAttribute(gemm_k<1>, cudaFuncAttributeMaxDynamicSharedMemorySize, GEMM_SMEM);
    cudaFuncSetAttribute(attn_mma, cudaFuncAttributeMaxDynamicSharedMemorySize, ATTN2_SMEM);

    // 0) single fused prologue: round x / w_qkv / w_out to tf32 + rope table
    prep_all<<<PREP_THREADS / 256, 256>>>(
        (const float4*)x, (const float4*)w_qkv, (const float4*)w_out,
        (float4*)p_x, (float4*)p_wqkv, (float4*)p_wout, p_rope);

    // 1) fused: qkv GEMM + RoPE(q,k) + V transpose  → g_Q, g_K, g_Vt
    gemm_k<1><<<dim3(QKV_N / 128, MROWS / 128), 256, GEMM_SMEM>>>(
        p_x, p_wqkv, nullptr, p_Q, p_K, p_Vt, p_rope, QKV_N, EE);
    // 2) flash attention (mma.sync tf32, cp.async pipelined, heavy-first 1D grid)
    attn_mma<<<(SS / 128) * HH * BB, 256, ATTN2_SMEM>>>(p_Q, p_K, p_Vt, p_y);
    // 3) out = y @ w_out^T
    gemm_k<0><<<dim3(EE / 128, MROWS / 128), 256, GEMM_SMEM>>>(
        p_y, p_wout, out, nullptr, nullptr, nullptr, nullptr, EE, EE);
}

// round 15
// speedup vs baseline: 1.1677x; 1.0005x over previous
#include <cuda_runtime.h>
#include <cuda_bf16.h>
#include <cstdint>
#include <math.h>

// Problem constants
#define BB 2
#define SS 2048
#define EE 2048
#define HH 16
#define DD 128
#define MROWS (BB * SS)          // 4096
#define QKV_N (3 * EE)           // 6144

// ---------------- scratch (device globals: allocation-free) ----------------
__device__ float g_x   [(size_t)MROWS * EE];            // tf32-rounded x
__device__ float g_wqkv[(size_t)QKV_N * EE];            // tf32-rounded w_qkv
__device__ float g_wout[(size_t)EE * EE];               // tf32-rounded w_out
__device__ float g_Q   [(size_t)BB * HH * SS * DD];     // [b,h,s,d] roped, scaled, tf32
__device__ float g_K   [(size_t)BB * HH * SS * DD];     // [b,h,s,d] roped, tf32
__device__ float g_Vt  [(size_t)BB * HH * DD * SS];     // [b,h,d,s] tf32
__device__ float g_y   [(size_t)MROWS * EE];            // [b,s,h,d], tf32-rounded
__device__ float2 g_rope[(size_t)SS * 64];              // (cos,sin) per (s, i)

// ======================= helpers ===========================================
__device__ __forceinline__ uint32_t smem_u32(const void* p) {
    uint32_t a;
    asm("{ .reg .u64 t; cvta.to.shared.u64 t, %1; cvt.u32.u64 %0, t; }"
        : "=r"(a) : "l"(p));
    return a;
}

__device__ __forceinline__ float to_tf32(float x) {
    uint32_t u;
    asm("cvt.rna.tf32.f32 %0, %1;" : "=r"(u) : "f"(x));
    return __uint_as_float(u);
}

__device__ __forceinline__ float4 round4(float4 v) {
    v.x = to_tf32(v.x); v.y = to_tf32(v.y);
    v.z = to_tf32(v.z); v.w = to_tf32(v.w);
    return v;
}

#define CPA16(dst, src) \
    asm volatile("cp.async.cg.shared.global [%0], [%1], 16;" :: "r"(dst), "l"(src))
#define CPA_COMMIT()  asm volatile("cp.async.commit_group;" ::: "memory")
#define CPA_WAIT1()   asm volatile("cp.async.wait_group 1;" ::: "memory")
#define CPA_WAIT0()   asm volatile("cp.async.wait_group 0;" ::: "memory")

#define LDSM4(r, addr)                                                        \
    asm volatile("ldmatrix.sync.aligned.m8n8.x4.shared.b16 {%0,%1,%2,%3}, [%4];" \
        : "=r"((r)[0]), "=r"((r)[1]), "=r"((r)[2]), "=r"((r)[3]) : "r"(addr))

#define MMA_TF32(c, a, b0, b1)                                                \
    asm volatile("mma.sync.aligned.m16n8k8.row.col.f32.tf32.tf32.f32 "        \
        "{%0,%1,%2,%3}, {%4,%5,%6,%7}, {%8,%9}, {%0,%1,%2,%3};"               \
        : "+f"((c)[0]), "+f"((c)[1]), "+f"((c)[2]), "+f"((c)[3])              \
        : "r"((a)[0]), "r"((a)[1]), "r"((a)[2]), "r"((a)[3]), "r"(b0), "r"(b1))

// ============ mma.sync tf32 GEMM: C[M,N] = A[M,K] @ B[N,K]^T ===============
// CTA 128x128, 256 thr / 8 warps (4m x 2n), warptile 32x64, 3-stage cp.async
// 2 CTAs per SM. FUSE=1: QKV epilogue (RoPE q/k, transpose v), FUSE=0: plain C.
#define GP 36                                // SMEM pitch (floats), %32==4
#define BOFF (128 * GP * 4)                  // B offset within stage (bytes)
#define STG_B ((128 + 128) * GP * 4)         // 36864 bytes
#define GEMM_SMEM (3 * STG_B)                // 110592 bytes
#define CP 136                               // epilogue staging pitch (floats)

__device__ __forceinline__ void g2s_stage(const float* A, const float* B, int K,
                                          uint32_t stg, int tid) {
#pragma unroll
    for (int j = 0; j < 4; j++) {            // A: 128 rows x 8 chunks
        int cid = tid + j * 256;
        int row = cid >> 3, chk = cid & 7;
        CPA16(stg + (uint32_t)(row * GP + chk * 4) * 4,
              A + (size_t)row * K + chk * 4);
    }
#pragma unroll
    for (int j = 0; j < 4; j++) {            // B: 128 rows x 8 chunks
        int cid = tid + j * 256;
        int row = cid >> 3, chk = cid & 7;
        CPA16(stg + BOFF + (uint32_t)(row * GP + chk * 4) * 4,
              B + (size_t)row * K + chk * 4);
    }
}

template<int FUSE>
__global__ __launch_bounds__(256, 2)
void gemm_k(const float* __restrict__ A, const float* __restrict__ B,
            float* __restrict__ C,
            float* __restrict__ Qo, float* __restrict__ Ko, float* __restrict__ Vo,
            const float2* __restrict__ rt, int N, int K) {
    extern __shared__ char smem[];
    const uint32_t sbase = smem_u32(smem);
    const int tid  = threadIdx.x;
    const int wid  = tid >> 5;
    const int lane = tid & 31;
    const int wm   = wid >> 1;               // 0..3 (32 rows)
    const int wn   = wid & 1;                // 0..1 (64 cols)
    const int m0 = blockIdx.y * 128;
    const int n0 = blockIdx.x * 128;
    const int iters = K >> 5;

    const float* Ab = A + (size_t)m0 * K;
    const float* Bb = B + (size_t)n0 * K;

    float c[2][8][4];
#pragma unroll
    for (int i = 0; i < 2; i++)
#pragma unroll
        for (int j = 0; j < 8; j++)
#pragma unroll
            for (int q = 0; q < 4; q++) c[i][j][q] = 0.f;

    const int sub = lane >> 3;
    const int r8  = lane & 7;
    const uint32_t aoff = (uint32_t)((wm * 32 + (sub & 1) * 8 + r8) * GP + (sub >> 1) * 4) * 4;
    const uint32_t boff = BOFF + (uint32_t)((wn * 64 + (sub >> 1) * 8 + r8) * GP + (sub & 1) * 4) * 4;

    g2s_stage(Ab, Bb, K, sbase, tid);                   CPA_COMMIT();
    g2s_stage(Ab + 32, Bb + 32, K, sbase + STG_B, tid); CPA_COMMIT();

    for (int i = 0; i < iters; i++) {
        CPA_WAIT1();
        __syncthreads();
        if (i + 2 < iters) {
            uint32_t stg = sbase + (uint32_t)((i + 2) % 3) * STG_B;
            g2s_stage(Ab + (i + 2) * 32, Bb + (i + 2) * 32, K, stg, tid);
            CPA_COMMIT();
        }
        const uint32_t ab = sbase + (uint32_t)(i % 3) * STG_B + aoff;
        const uint32_t bb = sbase + (uint32_t)(i % 3) * STG_B + boff;

#pragma unroll
        for (int kk = 0; kk < 4; kk++) {
            uint32_t a[2][4], bf[4][4];
#pragma unroll
            for (int im = 0; im < 2; im++)
                LDSM4(a[im], ab + (uint32_t)(im * 16 * GP) * 4 + kk * 32);
#pragma unroll
            for (int nt = 0; nt < 4; nt++)
                LDSM4(bf[nt], bb + (uint32_t)(nt * 16 * GP) * 4 + kk * 32);
#pragma unroll
            for (int im = 0; im < 2; im++)
#pragma unroll
                for (int jn = 0; jn < 8; jn++)
                    MMA_TF32(c[im][jn], a[im],
                             bf[jn >> 1][(jn & 1) * 2],
                             bf[jn >> 1][(jn & 1) * 2 + 1]);
        }
    }

    const int g = lane >> 2, q = lane & 3;

    if (FUSE == 0) {
#pragma unroll
        for (int im = 0; im < 2; im++)
#pragma unroll
            for (int jn = 0; jn < 8; jn++) {
                int row = m0 + wm * 32 + im * 16 + g;
                int col = n0 + wn * 64 + jn * 8 + q * 2;
                *(float2*)&C[(size_t)row * N + col]       = make_float2(c[im][jn][0], c[im][jn][1]);
                *(float2*)&C[(size_t)(row + 8) * N + col] = make_float2(c[im][jn][2], c[im][jn][3]);
            }
    } else {
        // ---- fused QKV epilogue: stage tile, apply RoPE / transpose ----
        CPA_WAIT0();
        __syncthreads();                      // all warps done with stage SMEM
        float* Cs = (float*)smem;             // [128][CP]
#pragma unroll
        for (int im = 0; im < 2; im++)
#pragma unroll
            for (int jn = 0; jn < 8; jn++) {
                int row = wm * 32 + im * 16 + g;
                int col = wn * 64 + jn * 8 + q * 2;
                *(float2*)&Cs[row * CP + col]       = make_float2(c[im][jn][0], c[im][jn][1]);
                *(float2*)&Cs[(row + 8) * CP + col] = make_float2(c[im][jn][2], c[im][jn][3]);
            }
        __syncthreads();

        const int hb   = n0 >> 7;             // 0..47
        const int type = hb >> 4;             // 0=q,1=k,2=v
        const int h    = hb & 15;
        const int b    = m0 >> 11;
        const int s0   = m0 & 2047;
        const size_t bh = (size_t)(b * HH + h);

        if (type < 2) {
            float* Out = (type == 0) ? Qo : Ko;
            const float scl = (type == 0) ? 0.088388347648318447f : 1.0f;
#pragma unroll
            for (int p = 0; p < 16; p++) {
                int idx = tid + p * 256;
                int row = idx >> 5, col = (idx & 31) * 4;
                int s = s0 + row;
                float4 v = *(float4*)&Cs[row * CP + col];
                float4 w = *(float4*)&Cs[row * CP + (col ^ 64)];
                float ov[4];
#pragma unroll
                for (int j = 0; j < 4; j++) {
                    int d = col + j;
                    float2 t = rt[s * 64 + (d & 63)];
                    float val  = (&v.x)[j];
                    float part = (&w.x)[j];
                    float r = (d < 64) ? -part : part;
                    ov[j] = to_tf32((val * t.x + r * t.y) * scl);
                }
                *(float4*)&Out[(bh * SS + s) * DD + col] =
                    make_float4(ov[0], ov[1], ov[2], ov[3]);
            }
        } else {
#pragma unroll
            for (int p = 0; p < 16; p++) {
                int idx = tid + p * 256;
                int d = idx >> 5, ch = idx & 31;
                float* vrow = Vo + (bh * DD + d) * SS + s0;
#pragma unroll
                for (int j = 0; j < 4; j++) {
                    int s = ch + j * 32;
                    vrow[s] = to_tf32(Cs[s * CP + d]);
                }
            }
        }
    }
}

// -------- fused prologue: tf32-round x / w_qkv / w_out + rope table --------
#define X_N4   (MROWS * EE / 4)              // 2097152
#define WQ_N4  (QKV_N * EE / 4)              // 3145728
#define WO_N4  (EE * EE / 4)                 // 1048576
#define ROPE_N (SS * 64)                     // 131072
#define PREP_THREADS ((X_N4 + WQ_N4 + WO_N4 + ROPE_N))

__global__ void prep_all(const float4* __restrict__ x, const float4* __restrict__ wq,
                         const float4* __restrict__ wo,
                         float4* __restrict__ ox, float4* __restrict__ owq,
                         float4* __restrict__ owo, float2* __restrict__ rt) {
    int i = blockIdx.x * 256 + threadIdx.x;
    if (i < X_N4) { ox[i] = round4(x[i]); return; }
    i -= X_N4;
    if (i < WQ_N4) { owq[i] = round4(wq[i]); return; }
    i -= WQ_N4;
    if (i < WO_N4) { owo[i] = round4(wo[i]); return; }
    i -= WO_N4;
    int f = i & 63, s = i >> 6;
    float theta = (float)s * exp2f(-0.20762050593045998f * (float)f);
    float sn, cs;
    sincosf(theta, &sn, &cs);
    rt[i] = make_float2(cs, sn);
}

// ---------------- Flash attention via mma.sync tf32 + cp.async -------------
// 1D grid of 512 CTAs, globally sorted heavy-first (qb=15 tiles launch first).
#define QP 132                               // pitch (floats) for Qs/Ks
#define PP 68                                // pitch for Vs/Ps
#define ATTN2_SMEM ((128 * QP + 64 * QP + 128 * PP + 128 * PP) * 4)

__global__ __launch_bounds__(256, 1)
void attn_mma(const float* __restrict__ Qg_, const float* __restrict__ Kg_,
              const float* __restrict__ Vt_, float* __restrict__ Y) {
    extern __shared__ float sm[];
    float* Qs = sm;                          // [128][QP]  rows=qrow cols=d
    float* Ks = Qs + 128 * QP;               // [64][QP]   rows=kcol cols=d
    float* Vs = Ks + 64 * QP;                // [128][PP]  rows=d    cols=kcol
    float* Ps = Vs + 128 * PP;               // [128][PP]  rows=qrow cols=kcol

    const int tid  = threadIdx.x;
    const int wid  = tid >> 5;
    const int lane = tid & 31;
    const int flat = blockIdx.x;                 // 0..511
    const int qb = (SS / 128 - 1) - (flat >> 5); // heavy qb first, all (h,b)
    const int hb = flat & 31;
    const int h  = hb & 15;
    const int b  = hb >> 4;
    const int q0 = qb * 128;

    const size_t bh = (size_t)(b * HH + h);
    const float* Qg = Qg_ + bh * SS * DD;    // [s][d] (scaled, tf32)
    const float* Kg = Kg_ + bh * SS * DD;    // [s][d] (tf32)
    const float* Vg = Vt_ + bh * DD * SS;    // [d][s] (tf32)

    const uint32_t qsb = smem_u32(Qs);
    const uint32_t ksb = smem_u32(Ks);
    const uint32_t vsb = smem_u32(Vs);

    // prologue: async Q tile (group 1), K(0) (group 2), V(0) (group 3)
#pragma unroll
    for (int p = 0; p < 16; p++) {           // Q: 128 rows x 32 chunks
        int c = tid + p * 256;
        int row = c >> 5, ch = c & 31;
        CPA16(qsb + (uint32_t)(row * QP + ch * 4) * 4,
              Qg + (size_t)(q0 + row) * DD + ch * 4);
    }
    CPA_COMMIT();
#pragma unroll
    for (int p = 0; p < 8; p++) {            // K: 64 rows x 32 chunks
        int c = tid + p * 256;
        int row = c >> 5, ch = c & 31;
        CPA16(ksb + (uint32_t)(row * QP + ch * 4) * 4,
              Kg + (size_t)row * DD + ch * 4);
    }
    CPA_COMMIT();
#pragma unroll
    for (int p = 0; p < 8; p++) {            // V: 128 rows x 16 chunks
        int c = tid + p * 256;
        int row = c >> 4, ch = c & 15;
        CPA16(vsb + (uint32_t)(row * PP + ch * 4) * 4,
              Vg + (size_t)row * SS + ch * 4);
    }
    CPA_COMMIT();

    const int sub = lane >> 3, r8 = lane & 7;
    const int g = lane >> 2, qq = lane & 3;
    const uint32_t a_q = qsb + (uint32_t)((wid * 16 + (sub & 1) * 8 + r8) * QP + (sub >> 1) * 4) * 4;
    const uint32_t b_k = ksb + (uint32_t)(((sub >> 1) * 8 + r8) * QP + (sub & 1) * 4) * 4;
    const uint32_t a_p = smem_u32(Ps) + (uint32_t)((wid * 16 + (sub & 1) * 8 + r8) * PP + (sub >> 1) * 4) * 4;
    const uint32_t b_v = vsb + (uint32_t)(((sub >> 1) * 8 + r8) * PP + (sub & 1) * 4) * 4;

    float o[16][4];
#pragma unroll
    for (int i = 0; i < 16; i++)
#pragma unroll
        for (int j = 0; j < 4; j++) o[i][j] = 0.f;
    float m0v = -1e30f, m1v = -1e30f, l0 = 0.f, l1 = 0.f;

    const int nkt = 2 * qb + 2;
    for (int kt = 0; kt < nkt; kt++) {
        const int k0 = kt * 64;
        const bool pf = (kt + 1 < nkt);

        // [A] K(kt) (and Q on kt=0) ready
        CPA_WAIT1();
        __syncthreads();

        // S = Q K^T
        float s[8][4];
#pragma unroll
        for (int i = 0; i < 8; i++)
#pragma unroll
            for (int j = 0; j < 4; j++) s[i][j] = 0.f;
#pragma unroll
        for (int kd = 0; kd < 16; kd++) {
            uint32_t a[4];
            LDSM4(a, a_q + kd * 32);
            uint32_t bf[4][4];
#pragma unroll
            for (int nt = 0; nt < 4; nt++)
                LDSM4(bf[nt], b_k + (uint32_t)(nt * 16 * QP) * 4 + kd * 32);
#pragma unroll
            for (int nt = 0; nt < 4; nt++) {
                MMA_TF32(s[nt * 2],     a, bf[nt][0], bf[nt][1]);
                MMA_TF32(s[nt * 2 + 1], a, bf[nt][2], bf[nt][3]);
            }
        }

        // [B] all warps done reading Ks -> prefetch K(kt+1)
        __syncthreads();
        if (pf) {
            int k1 = k0 + 64;
#pragma unroll
            for (int p = 0; p < 8; p++) {
                int c = tid + p * 256;
                int row = c >> 5, ch = c & 31;
                CPA16(ksb + (uint32_t)(row * QP + ch * 4) * 4,
                      Kg + (size_t)(k1 + row) * DD + ch * 4);
            }
            CPA_COMMIT();
        }

        // causal mask (only last two tiles)
        if (kt >= 2 * qb) {
            int row0 = q0 + wid * 16 + g;
#pragma unroll
            for (int j = 0; j < 8; j++) {
                int c = k0 + j * 8 + qq * 2;
                if (c     > row0)     s[j][0] = -1e30f;
                if (c + 1 > row0)     s[j][1] = -1e30f;
                if (c     > row0 + 8) s[j][2] = -1e30f;
                if (c + 1 > row0 + 8) s[j][3] = -1e30f;
            }
        }

        // online softmax
        float tm0 = -1e30f, tm1 = -1e30f;
#pragma unroll
        for (int j = 0; j < 8; j++) {
            tm0 = fmaxf(tm0, fmaxf(s[j][0], s[j][1]));
            tm1 = fmaxf(tm1, fmaxf(s[j][2], s[j][3]));
        }
        tm0 = fmaxf(tm0, __shfl_xor_sync(0xffffffffu, tm0, 1));
        tm0 = fmaxf(tm0, __shfl_xor_sync(0xffffffffu, tm0, 2));
        tm1 = fmaxf(tm1, __shfl_xor_sync(0xffffffffu, tm1, 1));
        tm1 = fmaxf(tm1, __shfl_xor_sync(0xffffffffu, tm1, 2));
        float mn0 = fmaxf(m0v, tm0), mn1 = fmaxf(m1v, tm1);
        float al0 = __expf(m0v - mn0), al1 = __expf(m1v - mn1);
        m0v = mn0; m1v = mn1;
        float rs0 = 0.f, rs1 = 0.f;
#pragma unroll
        for (int j = 0; j < 8; j++) {
            s[j][0] = __expf(s[j][0] - mn0);
            s[j][1] = __expf(s[j][1] - mn0);
            s[j][2] = __expf(s[j][2] - mn1);
            s[j][3] = __expf(s[j][3] - mn1);
            rs0 += s[j][0] + s[j][1];
            rs1 += s[j][2] + s[j][3];
        }
        rs0 += __shfl_xor_sync(0xffffffffu, rs0, 1);
        rs0 += __shfl_xor_sync(0xffffffffu, rs0, 2);
        rs1 += __shfl_xor_sync(0xffffffffu, rs1, 1);
        rs1 += __shfl_xor_sync(0xffffffffu, rs1, 2);
        l0 = l0 * al0 + rs0;
        l1 = l1 * al1 + rs1;
#pragma unroll
        for (int nt = 0; nt < 16; nt++) {
            o[nt][0] *= al0; o[nt][1] *= al0;
            o[nt][2] *= al1; o[nt][3] *= al1;
        }

        // stage P (warp-private rows), tf32-rounded
        {
            int pr0 = (wid * 16 + g) * PP;
#pragma unroll
            for (int j = 0; j < 8; j++) {
                *(float2*)&Ps[pr0 + j * 8 + qq * 2] =
                    make_float2(to_tf32(s[j][0]), to_tf32(s[j][1]));
                *(float2*)&Ps[pr0 + 8 * PP + j * 8 + qq * 2] =
                    make_float2(to_tf32(s[j][2]), to_tf32(s[j][3]));
            }
        }
        __syncwarp();

        // [C] V(kt) ready (leave K(kt+1) in flight if prefetching)
        if (pf) { CPA_WAIT1(); } else { CPA_WAIT0(); }
        __syncthreads();

        // O += P @ V
#pragma unroll
        for (int jk = 0; jk < 8; jk++) {
            uint32_t a[4];
            LDSM4(a, a_p + jk * 32);
#pragma unroll
            for (int nt = 0; nt < 8; nt++) {
                uint32_t bf[4];
                LDSM4(bf, b_v + (uint32_t)(nt * 16 * PP) * 4 + jk * 32);
                MMA_TF32(o[nt * 2],     a, bf[0], bf[1]);
                MMA_TF32(o[nt * 2 + 1], a, bf[2], bf[3]);
            }
        }

        // [D] all warps done reading Vs -> prefetch V(kt+1)
        __syncthreads();
        if (pf) {
            int k1 = k0 + 64;
#pragma unroll
            for (int p = 0; p < 8; p++) {
                int c = tid + p * 256;
                int row = c >> 4, ch = c & 15;
                CPA16(vsb + (uint32_t)(row * PP + ch * 4) * 4,
                      Vg + (size_t)row * SS + k1 + ch * 4);
            }
            CPA_COMMIT();
        }
    }

    // normalize + tf32-round + write Y [b,s,h,d]
    float i0 = 1.f / l0, i1 = 1.f / l1;
    int row0 = q0 + wid * 16 + g;
    size_t base0 = ((size_t)b * SS + row0) * EE + h * 128;
    size_t base1 = base0 + (size_t)8 * EE;
#pragma unroll
    for (int nt = 0; nt < 16; nt++) {
        int col = nt * 8 + qq * 2;
        *(float2*)&Y[base0 + col] =
            make_float2(to_tf32(o[nt][0] * i0), to_tf32(o[nt][1] * i0));
        *(float2*)&Y[base1 + col] =
            make_float2(to_tf32(o[nt][2] * i1), to_tf32(o[nt][3] * i1));
    }
}

// ---------------- launch -----------------------------------------------------
extern "C" void kernel_launch(void* const* d_in, const int* in_sizes, int n_in,
                              void* d_out, int out_size) {
    const float* x     = (const float*)d_in[0];
    const float* w_qkv = (const float*)d_in[1];
    const float* w_out = (const float*)d_in[2];
    float* out = (float*)d_out;

    float *p_x, *p_wqkv, *p_wout, *p_Q, *p_K, *p_Vt, *p_y;
    float2* p_rope;
    cudaGetSymbolAddress((void**)&p_x,    g_x);
    cudaGetSymbolAddress((void**)&p_wqkv, g_wqkv);
    cudaGetSymbolAddress((void**)&p_wout, g_wout);
    cudaGetSymbolAddress((void**)&p_Q,    g_Q);
    cudaGetSymbolAddress((void**)&p_K,    g_K);
    cudaGetSymbolAddress((void**)&p_Vt,   g_Vt);
    cudaGetSymbolAddress((void**)&p_y,    g_y);
    cudaGetSymbolAddress((void**)&p_rope, g_rope);

    cudaFuncSetAttribute(gemm_k<0>, cudaFuncAttributeMaxDynamicSharedMemorySize, GEMM_SMEM);
    cudaFuncSetAttribute(gemm_k<1>, cudaFuncAttributeMaxDynamicSharedMemorySize, GEMM_SMEM);
    cudaFuncSetAttribute(attn_mma, cudaFuncAttributeMaxDynamicSharedMemorySize, ATTN2_SMEM);

    // 0) single fused prologue: round x / w_qkv / w_out to tf32 + rope table
    prep_all<<<PREP_THREADS / 256, 256>>>(
        (const float4*)x, (const float4*)w_qkv, (const float4*)w_out,
        (float4*)p_x, (float4*)p_wqkv, (float4*)p_wout, p_rope);

    // 1) fused: qkv GEMM + RoPE(q,k) + V transpose  → g_Q, g_K, g_Vt
    gemm_k<1><<<dim3(QKV_N / 128, MROWS / 128), 256, GEMM_SMEM>>>(
        p_x, p_wqkv, nullptr, p_Q, p_K, p_Vt, p_rope, QKV_N, EE);
    // 2) flash attention (mma.sync tf32, cp.async pipelined, heavy-first 1D grid)
    attn_mma<<<(SS / 128) * HH * BB, 256, ATTN2_SMEM>>>(p_Q, p_K, p_Vt, p_y);
    // 3) out = y @ w_out^T
    gemm_k<0><<<dim3(EE / 128, MROWS / 128), 256, GEMM_SMEM>>>(
        p_y, p_wout, out, nullptr, nullptr, nullptr, nullptr, EE, EE);
}